// round 12
// baseline (speedup 1.0000x reference)
#include <cuda_runtime.h>

#define NB 4
#define LL 4096
#define KMAX 64
#define NCODES 256

// Dynamic smem layout (bytes):
//   rows   float [NCODES*KMAX]  @ 0      (65536)
//   hist   ushort[8*NCODES]     @ 65536  (4096)   per-warp counts -> bases
//   scnt   ushort[NCODES]       @ 69632  (512)    total per code
//   scodes uchar [LL]           @ 70144  (4096)   key codes (overflow path)
//   qcodes uchar [128]          @ 74240  (128)
//   oflow  int                  @ 74368  (4)
#define SMEM_TOTAL 74372

__device__ __forceinline__ int pack8(float4 a, float4 c) {
    return (a.x > 0.f)        | ((a.y > 0.f) << 1) |
           ((a.z > 0.f) << 2) | ((a.w > 0.f) << 3) |
           ((c.x > 0.f) << 4) | ((c.y > 0.f) << 5) |
           ((c.z > 0.f) << 6) | ((c.w > 0.f) << 7);
}

__global__ void __launch_bounds__(256)
k_all(const float* __restrict__ key_up,
      const float* __restrict__ query_up,
      float* __restrict__ out) {
    extern __shared__ char sm[];
    float*          rows   = (float*)sm;
    unsigned short* hist   = (unsigned short*)(sm + 65536);
    unsigned short* scnt   = (unsigned short*)(sm + 69632);
    unsigned char*  scodes = (unsigned char*)(sm + 70144);
    unsigned char*  qcodes = (unsigned char*)(sm + 74240);
    int*            oflow  = (int*)(sm + 74368);

    int tid  = threadIdx.x;
    int warp = tid >> 5;
    int lane = tid & 31;
    int b    = blockIdx.x >> 5;       // batch
    int chunk= blockIdx.x & 31;       // 128-query chunk within batch

    // Early query prefetch (overlaps init + key phase).
    float4 qv = ((const float4*)query_up)[(b * LL + chunk * 128) * 2 + tid];

    // ---- init: rows = -1.0f, hist/scnt = 0 ----
    float4 neg1 = make_float4(-1.f, -1.f, -1.f, -1.f);
    #pragma unroll
    for (int i = 0; i < 16; i++)
        ((float4*)rows)[tid + i * 256] = neg1;
    #pragma unroll
    for (int i = 0; i < 5; i++) {
        int idx = tid + i * 256;
        if (idx < 1152) ((int*)hist)[idx] = 0;    // hist(4096B)+scnt(512B)
    }
    if (tid == 0) *oflow = 0;
    __syncthreads();

    // ---- count + within-warp rank (no atomics) ----
    // Warp w owns keys [w*512, w*512+512): j ascending across rounds/lanes.
    unsigned char  myc   [16];
    unsigned short myrank[16];
    const float4* kb = (const float4*)(key_up + (size_t)b * LL * 8);
    unsigned lt = (1u << lane) - 1u;
    #pragma unroll
    for (int k = 0; k < 16; k++) {
        int j = warp * 512 + k * 32 + lane;
        float4 a  = kb[j * 2];
        float4 c4 = kb[j * 2 + 1];
        int c = pack8(a, c4);
        scodes[j] = (unsigned char)c;
        unsigned mask = __match_any_sync(0xffffffffu, c);
        int before = (int)hist[warp * NCODES + c];
        myc[k]    = (unsigned char)c;
        myrank[k] = (unsigned short)(before + __popc(mask & lt));
        if ((mask & lt) == 0)                     // lowest lane of group
            hist[warp * NCODES + c] = (unsigned short)(before + __popc(mask));
        __syncwarp();                             // order hist across rounds
    }

    // Query codes: lane pairs combine nibbles; even lane stores.
    {
        int nib = (qv.x > 0.f)        | ((qv.y > 0.f) << 1) |
                  ((qv.z > 0.f) << 2) | ((qv.w > 0.f) << 3);
        int pr = __shfl_xor_sync(0xffffffffu, nib, 1);
        int code = (lane & 1) ? (pr | (nib << 4)) : (nib | (pr << 4));
        if (!(tid & 1)) qcodes[tid >> 1] = (unsigned char)code;
    }
    __syncthreads();

    // ---- exclusive prefix over the 8 warp-histograms, per code ----
    if (tid < NCODES) {
        int tot = 0;
        #pragma unroll
        for (int w = 0; w < 8; w++) {
            int t = hist[w * NCODES + tid];
            hist[w * NCODES + tid] = (unsigned short)tot;  // becomes base
            tot += t;
        }
        scnt[tid] = (unsigned short)tot;
        if (tot > KMAX) *oflow = 1;
    }
    __syncthreads();

    // ---- write rows: pos = (64-n) + base[warp][c] + within-warp rank ----
    #pragma unroll
    for (int k = 0; k < 16; k++) {
        int c = myc[k];
        int n = scnt[c];
        if (n <= KMAX) {
            int pos = (KMAX - n) + (int)hist[warp * NCODES + c] + (int)myrank[k];
            rows[c * KMAX + pos] = (float)(warp * 512 + k * 32 + lane);
        }
    }

    // ---- overflow fallback (statistically impossible; uniform branch) ----
    if (*oflow) {
        __syncthreads();
        if (warp == 0) {
            for (int c = 0; c < NCODES; c++) {
                if ((int)scnt[c] > KMAX) {
                    int m = 0;
                    for (int r = 0; r < 32 && m < KMAX; r++) {
                        uchar4 v = ((const uchar4*)scodes)[r * 32 + lane];
                        unsigned m0 = __ballot_sync(0xffffffffu, v.x == c);
                        unsigned m1 = __ballot_sync(0xffffffffu, v.y == c);
                        unsigned m2 = __ballot_sync(0xffffffffu, v.z == c);
                        unsigned m3 = __ballot_sync(0xffffffffu, v.w == c);
                        int p = m + __popc(m0 & lt) + __popc(m1 & lt)
                                  + __popc(m2 & lt) + __popc(m3 & lt);
                        int j0 = (r * 32 + lane) * 4;
                        if (v.x == c) { if (p < KMAX) rows[c*KMAX+p] = (float)j0;     p++; }
                        if (v.y == c) { if (p < KMAX) rows[c*KMAX+p] = (float)(j0+1); p++; }
                        if (v.z == c) { if (p < KMAX) rows[c*KMAX+p] = (float)(j0+2); p++; }
                        if (v.w == c) { if (p < KMAX) rows[c*KMAX+p] = (float)(j0+3); p++; }
                        m += __popc(m0) + __popc(m1) + __popc(m2) + __popc(m3);
                    }
                }
            }
        }
    }
    __syncthreads();

    // ---- emit: 2 queries per warp per iter, 1 float4/lane, coalesced ----
    int qbase = b * LL + chunk * 128;
    #pragma unroll
    for (int it = 0; it < 8; it++) {
        int q    = it * 16 + warp * 2 + (lane >> 4);
        int code = (int)qcodes[q];
        float4 v = ((const float4*)(rows + code * KMAX))[lane & 15];
        ((float4*)out)[(size_t)(qbase + q) * 16 + (lane & 15)] = v;
    }
}

extern "C" void kernel_launch(void* const* d_in, const int* in_sizes, int n_in,
                              void* d_out, int out_size) {
    // Identify inputs by element count (robust to metadata ordering).
    const float* query_up = nullptr;
    const float* key_up   = nullptr;
    for (int i = 0; i < n_in; i++) {
        if (in_sizes[i] == NB * LL * 8) {
            if (!query_up)      query_up = (const float*)d_in[i];
            else if (!key_up)   key_up   = (const float*)d_in[i];
        }
    }
    if (!query_up || !key_up) {
        query_up = (const float*)d_in[0];
        key_up   = (const float*)d_in[1];
    }
    float* out = (float*)d_out;

    static int smem_set = 0;
    if (!smem_set) {
        cudaFuncSetAttribute(k_all, cudaFuncAttributeMaxDynamicSharedMemorySize,
                             SMEM_TOTAL);
        smem_set = 1;
    }
    k_all<<<NB * 32, 256, SMEM_TOTAL>>>(key_up, query_up, out);
}

// round 13
// speedup vs baseline: 1.1633x; 1.1633x over previous
#include <cuda_runtime.h>

#define NB 4
#define LL 4096
#define KMAX 64
#define NCODES 256

// Scratch (no allocations). g_bits zero-initialized at load; k_rank zeroes the
// words it consumed each run -> deterministic across graph replays.
__device__ unsigned int g_bits[NB * NCODES * (LL / 32)];  // 512 KB bitmaps
__device__ float        g_rows[NB * NCODES * KMAX];       // 256 KB rows

__device__ __forceinline__ int pack8(float4 a, float4 c) {
    return (a.x > 0.f)        | ((a.y > 0.f) << 1) |
           ((a.z > 0.f) << 2) | ((a.w > 0.f) << 3) |
           ((c.x > 0.f) << 4) | ((c.y > 0.f) << 5) |
           ((c.z > 0.f) << 6) | ((c.w > 0.f) << 7);
}

// K1: one thread per key: load 32B, pack code, set bit j in the (batch,code)
// bitmap. atomicOr return value unused -> REDG.OR, fire-and-forget: the 318cyc
// atomic round-trip is NOT in the dependency chain.
__global__ void __launch_bounds__(128)
k_scatter(const float* __restrict__ key_up) {
    int t = blockIdx.x * 128 + threadIdx.x;              // key id 0..16383
    const float4* p = reinterpret_cast<const float4*>(key_up) + t * 2;
    int code = pack8(p[0], p[1]);
    int j = t & (LL - 1);
    unsigned int* w = g_bits + ((((t >> 12) << 8) | code) * (LL / 32)) + (j >> 5);
    atomicOr(w, 1u << (j & 31));
}

// K2: one warp per (batch,code). Read the 4096-bit bitmap (uint4 per lane,
// 512B coalesced), zero it in place, popc+shfl-scan for ranks, extract set
// bits in ascending j order into the padded row:
//   pad = max(0, 64-n) leading -1s, then min(n,64) smallest j ascending.
// Handles n>64 natively (first 64 set bits, pad=0) - no fallback needed.
__global__ void __launch_bounds__(128)
k_rank() {
    int gw   = blockIdx.x * 4 + (threadIdx.x >> 5);      // cidx 0..1023
    int lane = threadIdx.x & 31;

    uint4* bp = reinterpret_cast<uint4*>(g_bits + gw * (LL / 32));
    uint4 wv = bp[lane];                                 // words 4l..4l+3
    bp[lane] = make_uint4(0u, 0u, 0u, 0u);               // self-reset

    int c = __popc(wv.x) + __popc(wv.y) + __popc(wv.z) + __popc(wv.w);
    // inclusive shfl scan -> exclusive base + total
    int inc = c;
    #pragma unroll
    for (int d = 1; d < 32; d <<= 1) {
        int u = __shfl_up_sync(0xffffffffu, inc, d);
        if (lane >= d) inc += u;
    }
    int n    = __shfl_sync(0xffffffffu, inc, 31);
    int rank = inc - c;
    int pad  = n < KMAX ? KMAX - n : 0;

    float* row = g_rows + gw * KMAX;
    if (lane      < pad) row[lane]      = -1.0f;
    if (lane + 32 < pad) row[lane + 32] = -1.0f;

    unsigned int ws[4] = {wv.x, wv.y, wv.z, wv.w};
    #pragma unroll
    for (int i = 0; i < 4; i++) {
        unsigned int w = ws[i];
        int jb = (lane * 4 + i) * 32;
        while (w) {
            int bit = __ffs(w) - 1;
            int pos = pad + rank;
            if (pos < KMAX) row[pos] = (float)(jb + bit);
            rank++;
            w &= w - 1;
        }
    }
}

// K3: flat emit, one output float4 per thread (262,144 threads). The 16
// threads of a query cooperatively pack its code (lanes r<2 load the two
// float4s, nibble-combine via 2 shfls), then each gathers one float4 of the
// row (L2-hot) and stores fully coalesced to DRAM.
__global__ void __launch_bounds__(256)
k_emit(const float* __restrict__ query_up, float* __restrict__ out) {
    int i    = blockIdx.x * 256 + threadIdx.x;           // 0..262143
    int qi   = i >> 4;                                   // query id
    int r    = i & 15;                                   // float4 within row
    int lane = threadIdx.x & 31;
    int b    = qi >> 12;

    int part = 0;
    if (r < 2) {
        float4 p = reinterpret_cast<const float4*>(query_up)[qi * 2 + r];
        int nib = (p.x > 0.f)        | ((p.y > 0.f) << 1) |
                  ((p.z > 0.f) << 2) | ((p.w > 0.f) << 3);
        part = (r == 0) ? nib : (nib << 4);
    }
    part |= __shfl_xor_sync(0xffffffffu, part, 1);       // pair-combine
    int code = __shfl_sync(0xffffffffu, part, lane & ~15); // group broadcast

    float4 v = reinterpret_cast<const float4*>(
                   g_rows + (((b << 8) | code) * KMAX))[r];
    reinterpret_cast<float4*>(out)[i] = v;
}

extern "C" void kernel_launch(void* const* d_in, const int* in_sizes, int n_in,
                              void* d_out, int out_size) {
    // Identify inputs by element count (robust to metadata ordering).
    const float* query_up = nullptr;
    const float* key_up   = nullptr;
    for (int i = 0; i < n_in; i++) {
        if (in_sizes[i] == NB * LL * 8) {
            if (!query_up)      query_up = (const float*)d_in[i];
            else if (!key_up)   key_up   = (const float*)d_in[i];
        }
    }
    if (!query_up || !key_up) {
        query_up = (const float*)d_in[0];
        key_up   = (const float*)d_in[1];
    }
    float* out = (float*)d_out;

    k_scatter<<<128, 128>>>(key_up);        // 16K threads, REDG.OR bitmap
    k_rank<<<256, 128>>>();                 // 1024 warps, bitmap -> rows
    k_emit<<<1024, 256>>>(query_up, out);   // 262,144 threads, gather+store
}